// round 1
// baseline (speedup 1.0000x reference)
#include <cuda_runtime.h>

#define NB 32
#define ND 64
#define NT 4096
#define NK 1024
#define NTOK (NB*NT)          // 131072 tokens
#define OUTQ (NB*ND*NT)       // 8388608 quantized elements
#define CHUNK 128             // codes per smem chunk (32 KB)
#define TPB 256
#define NPART 2048

// Scratch (no allocations allowed in kernel_launch)
__device__ int   g_idx[NTOK];
__device__ float g_part[NPART];

static __device__ __forceinline__ unsigned long long pack2(float lo, float hi) {
    unsigned long long r;
    asm("mov.b64 %0, {%1, %2};" : "=l"(r) : "f"(lo), "f"(hi));
    return r;
}
static __device__ __forceinline__ float2 unpack2(unsigned long long v) {
    float2 f;
    asm("mov.b64 {%0, %1}, %2;" : "=f"(f.x), "=f"(f.y) : "l"(v));
    return f;
}
// packed dual-fp32 FMA (Blackwell f32x2) — 2x FFMA throughput vs FFMA-3reg
static __device__ __forceinline__ void ffma2(unsigned long long &acc,
                                             unsigned long long a,
                                             unsigned long long b) {
    asm("fma.rn.f32x2 %0, %1, %2, %3;" : "=l"(acc) : "l"(a), "l"(b), "l"(acc));
}

// ---------------------------------------------------------------------------
// Kernel 1: per-token argmax over the codebook.
// argmax_k (x.e_k / ||x||) == argmax_k (x.e_k)  -> skip normalization entirely.
// One thread = one token. x in 32 packed f32x2 registers. Codebook streamed
// through smem in 128-code chunks, read as uniform (broadcast) LDS.128.
// ---------------------------------------------------------------------------
__global__ void __launch_bounds__(TPB, 2) vq_argmax_kernel(
        const float* __restrict__ in, const float* __restrict__ emb,
        float* __restrict__ out)
{
    __shared__ float4 se[CHUNK * 16];   // 128 codes x 64 floats = 32 KB

    const int b = blockIdx.x >> 4;                       // 16 blocks per batch
    const int t = ((blockIdx.x & 15) << 8) + threadIdx.x;
    const float* xin = in + (size_t)b * ND * NT + t;     // layout [B, D, T]

    unsigned long long xp[32];
#pragma unroll
    for (int j = 0; j < 32; j++)
        xp[j] = pack2(xin[(size_t)(2*j) * NT], xin[(size_t)(2*j+1) * NT]);

    float best = -3.0e38f;
    int   bidx = 0;

    for (int c = 0; c < NK; c += CHUNK) {
        const float4* g = reinterpret_cast<const float4*>(emb + c * ND);
#pragma unroll
        for (int i = 0; i < (CHUNK * 16) / TPB; i++)
            se[threadIdx.x + i * TPB] = g[threadIdx.x + i * TPB];
        __syncthreads();

        const unsigned long long* sp =
            reinterpret_cast<const unsigned long long*>(se);
#pragma unroll 2
        for (int k = 0; k < CHUNK; k++) {
            const ulonglong2* row =
                reinterpret_cast<const ulonglong2*>(sp + k * 32);
            unsigned long long a0 = 0ull, a1 = 0ull, a2 = 0ull, a3 = 0ull;
#pragma unroll
            for (int j = 0; j < 8; j++) {
                ulonglong2 e0 = row[2*j];
                ulonglong2 e1 = row[2*j + 1];
                ffma2(a0, xp[4*j + 0], e0.x);
                ffma2(a1, xp[4*j + 1], e0.y);
                ffma2(a2, xp[4*j + 2], e1.x);
                ffma2(a3, xp[4*j + 3], e1.y);
            }
            float2 f0 = unpack2(a0), f1 = unpack2(a1);
            float2 f2 = unpack2(a2), f3 = unpack2(a3);
            float val = ((f0.x + f0.y) + (f1.x + f1.y))
                      + ((f2.x + f2.y) + (f3.x + f3.y));
            if (val > best) { best = val; bidx = c + k; }   // first-max, like jnp.argmax
        }
        __syncthreads();
    }

    const int n = b * NT + t;
    g_idx[n] = bidx;
    out[OUTQ + 2 + n] = (float)bidx;   // idx output section
}

// ---------------------------------------------------------------------------
// Kernel 2: gather quantized output [B,D,T] + squared-error partials.
// commitment_loss == codebook_loss forward == mean((flat - emb_unnorm[idx])^2)
// ---------------------------------------------------------------------------
__global__ void __launch_bounds__(TPB) vq_gather_loss_kernel(
        const float* __restrict__ in, const float* __restrict__ emb,
        const float* __restrict__ embu, float* __restrict__ out)
{
    float lsum = 0.f;
    for (int i = blockIdx.x * TPB + threadIdx.x; i < OUTQ; i += NPART * TPB) {
        int t  = i & (NT - 1);
        int bd = i >> 12;
        int d  = bd & (ND - 1);
        int b  = bd >> 6;
        int code = g_idx[b * NT + t];
        out[i] = emb[code * ND + d];
        float diff = in[i] - embu[code * ND + d];
        lsum += diff * diff;
    }
    // block reduce -> one partial per block (no global atomics)
#pragma unroll
    for (int o = 16; o; o >>= 1) lsum += __shfl_xor_sync(0xffffffffu, lsum, o);
    __shared__ float ws[TPB / 32];
    if ((threadIdx.x & 31) == 0) ws[threadIdx.x >> 5] = lsum;
    __syncthreads();
    if (threadIdx.x < 32) {
        float v = (threadIdx.x < TPB / 32) ? ws[threadIdx.x] : 0.f;
#pragma unroll
        for (int o = 4; o; o >>= 1) v += __shfl_xor_sync(0xffffffffu, v, o);
        if (threadIdx.x == 0) g_part[blockIdx.x] = v;
    }
}

// ---------------------------------------------------------------------------
// Kernel 3: final reduction of loss partials (double precision), write scalars.
// ---------------------------------------------------------------------------
__global__ void vq_finalize_kernel(float* __restrict__ out)
{
    __shared__ double sd[TPB];
    double s = 0.0;
    for (int i = threadIdx.x; i < NPART; i += TPB) s += (double)g_part[i];
    sd[threadIdx.x] = s;
    __syncthreads();
    for (int o = TPB / 2; o; o >>= 1) {
        if (threadIdx.x < o) sd[threadIdx.x] += sd[threadIdx.x + o];
        __syncthreads();
    }
    if (threadIdx.x == 0) {
        float m = (float)(sd[0] / (double)OUTQ);
        out[OUTQ]     = m;   // commitment_loss
        out[OUTQ + 1] = m;   // codebook_loss (numerically identical forward)
    }
}

extern "C" void kernel_launch(void* const* d_in, const int* in_sizes, int n_in,
                              void* d_out, int out_size) {
    const float* in   = (const float*)d_in[0];   // [32, 64, 4096] fp32
    const float* emb  = (const float*)d_in[1];   // [1024, 64] fp32 (pre-normalized)
    const float* embu = (const float*)d_in[2];   // [1024, 64] fp32
    float* out = (float*)d_out;

    vq_argmax_kernel<<<(NB * NT) / TPB, TPB>>>(in, emb, out);
    vq_gather_loss_kernel<<<NPART, TPB>>>(in, emb, embu, out);
    vq_finalize_kernel<<<1, TPB>>>(out);
}

// round 2
// speedup vs baseline: 1.1841x; 1.1841x over previous
#include <cuda_runtime.h>

#define NB 32
#define ND 64
#define NT 4096
#define NK 1024
#define NTOK (NB*NT)          // 131072 tokens
#define OUTQ (NB*ND*NT)       // 8388608 quantized elements
#define CHUNK 128             // codes per smem chunk (32 KB)
#define ATPB 128              // argmax threads per block
#define TPB 256
#define NPART 2048

// Scratch (no allocations allowed in kernel_launch)
__device__ int   g_idx[NTOK];
__device__ float g_part[NPART];

static __device__ __forceinline__ unsigned long long pack2(float lo, float hi) {
    unsigned long long r;
    asm("mov.b64 %0, {%1, %2};" : "=l"(r) : "f"(lo), "f"(hi));
    return r;
}
static __device__ __forceinline__ float2 unpack2(unsigned long long v) {
    float2 f;
    asm("mov.b64 {%0, %1}, %2;" : "=f"(f.x), "=f"(f.y) : "l"(v));
    return f;
}
// packed dual-fp32 FMA / ADD (Blackwell f32x2) — 2x throughput vs scalar
static __device__ __forceinline__ void ffma2(unsigned long long &acc,
                                             unsigned long long a,
                                             unsigned long long b) {
    asm("fma.rn.f32x2 %0, %1, %2, %3;" : "=l"(acc) : "l"(a), "l"(b), "l"(acc));
}
static __device__ __forceinline__ unsigned long long fadd2(unsigned long long a,
                                                           unsigned long long b) {
    unsigned long long r;
    asm("add.rn.f32x2 %0, %1, %2;" : "=l"(r) : "l"(a), "l"(b));
    return r;
}

// ---------------------------------------------------------------------------
// Kernel 1: per-token argmax over the codebook.
// argmax_k (x.e_k / ||x||) == argmax_k (x.e_k)  -> skip normalization.
// TWO tokens per thread: each 16xLDS.128 code row feeds 64 FFMA2 (was 32),
// halving smem-wavefront demand per FLOP (R1 showed L1=82% / fma=45%).
// ---------------------------------------------------------------------------
__global__ void __launch_bounds__(ATPB, 2) vq_argmax_kernel(
        const float* __restrict__ in, const float* __restrict__ emb,
        float* __restrict__ out)
{
    __shared__ float4 se[CHUNK * 16];   // 128 codes x 64 floats = 32 KB

    const int b  = blockIdx.x >> 4;                        // 16 blocks per batch
    const int t0 = ((blockIdx.x & 15) << 8) + threadIdx.x; // token 0
    const int t1 = t0 + ATPB;                              // token 1
    const float* x0 = in + (size_t)b * ND * NT + t0;       // layout [B, D, T]
    const float* x1 = in + (size_t)b * ND * NT + t1;

    unsigned long long xp[64];
#pragma unroll
    for (int j = 0; j < 32; j++) {
        xp[j]      = pack2(x0[(size_t)(2*j) * NT], x0[(size_t)(2*j+1) * NT]);
        xp[32 + j] = pack2(x1[(size_t)(2*j) * NT], x1[(size_t)(2*j+1) * NT]);
    }

    float best0 = -3.0e38f, best1 = -3.0e38f;
    int   idx0 = 0, idx1 = 0;

    for (int c = 0; c < NK; c += CHUNK) {
        const float4* g = reinterpret_cast<const float4*>(emb + c * ND);
#pragma unroll
        for (int i = 0; i < (CHUNK * 16) / ATPB; i++)
            se[threadIdx.x + i * ATPB] = g[threadIdx.x + i * ATPB];
        __syncthreads();

        const unsigned long long* sp =
            reinterpret_cast<const unsigned long long*>(se);
#pragma unroll 2
        for (int k = 0; k < CHUNK; k++) {
            const ulonglong2* row =
                reinterpret_cast<const ulonglong2*>(sp + k * 32);
            unsigned long long a0 = 0ull, a1 = 0ull, a2 = 0ull, a3 = 0ull;
            unsigned long long b0 = 0ull, b1 = 0ull, b2 = 0ull, b3 = 0ull;
#pragma unroll
            for (int j = 0; j < 8; j++) {
                ulonglong2 e0 = row[2*j];
                ulonglong2 e1 = row[2*j + 1];
                ffma2(a0, xp[4*j + 0], e0.x);
                ffma2(a1, xp[4*j + 1], e0.y);
                ffma2(a2, xp[4*j + 2], e1.x);
                ffma2(a3, xp[4*j + 3], e1.y);
                ffma2(b0, xp[32 + 4*j + 0], e0.x);
                ffma2(b1, xp[32 + 4*j + 1], e0.y);
                ffma2(b2, xp[32 + 4*j + 2], e1.x);
                ffma2(b3, xp[32 + 4*j + 3], e1.y);
            }
            unsigned long long sa = fadd2(fadd2(a0, a1), fadd2(a2, a3));
            unsigned long long sb = fadd2(fadd2(b0, b1), fadd2(b2, b3));
            float2 fa = unpack2(sa);
            float2 fb = unpack2(sb);
            float v0 = fa.x + fa.y;
            float v1 = fb.x + fb.y;
            if (v0 > best0) { best0 = v0; idx0 = c + k; }  // first-max, like jnp.argmax
            if (v1 > best1) { best1 = v1; idx1 = c + k; }
        }
        __syncthreads();
    }

    const int n0 = b * NT + t0;
    const int n1 = b * NT + t1;
    g_idx[n0] = idx0;
    g_idx[n1] = idx1;
    out[OUTQ + 2 + n0] = (float)idx0;   // idx output section
    out[OUTQ + 2 + n1] = (float)idx1;
}

// ---------------------------------------------------------------------------
// Kernel 2: gather quantized output [B,D,T] + squared-error partials.
// commitment_loss == codebook_loss forward == mean((flat - emb_unnorm[idx])^2)
// ---------------------------------------------------------------------------
__global__ void __launch_bounds__(TPB) vq_gather_loss_kernel(
        const float* __restrict__ in, const float* __restrict__ emb,
        const float* __restrict__ embu, float* __restrict__ out)
{
    float lsum = 0.f;
    for (int i = blockIdx.x * TPB + threadIdx.x; i < OUTQ; i += NPART * TPB) {
        int t  = i & (NT - 1);
        int bd = i >> 12;
        int d  = bd & (ND - 1);
        int b  = bd >> 6;
        int code = g_idx[b * NT + t];
        out[i] = emb[code * ND + d];
        float diff = in[i] - embu[code * ND + d];
        lsum += diff * diff;
    }
    // block reduce -> one partial per block (no global atomics)
#pragma unroll
    for (int o = 16; o; o >>= 1) lsum += __shfl_xor_sync(0xffffffffu, lsum, o);
    __shared__ float ws[TPB / 32];
    if ((threadIdx.x & 31) == 0) ws[threadIdx.x >> 5] = lsum;
    __syncthreads();
    if (threadIdx.x < 32) {
        float v = (threadIdx.x < TPB / 32) ? ws[threadIdx.x] : 0.f;
#pragma unroll
        for (int o = 4; o; o >>= 1) v += __shfl_xor_sync(0xffffffffu, v, o);
        if (threadIdx.x == 0) g_part[blockIdx.x] = v;
    }
}

// ---------------------------------------------------------------------------
// Kernel 3: final reduction of loss partials (double precision), write scalars.
// ---------------------------------------------------------------------------
__global__ void vq_finalize_kernel(float* __restrict__ out)
{
    __shared__ double sd[TPB];
    double s = 0.0;
    for (int i = threadIdx.x; i < NPART; i += TPB) s += (double)g_part[i];
    sd[threadIdx.x] = s;
    __syncthreads();
    for (int o = TPB / 2; o; o >>= 1) {
        if (threadIdx.x < o) sd[threadIdx.x] += sd[threadIdx.x + o];
        __syncthreads();
    }
    if (threadIdx.x == 0) {
        float m = (float)(sd[0] / (double)OUTQ);
        out[OUTQ]     = m;   // commitment_loss
        out[OUTQ + 1] = m;   // codebook_loss (numerically identical forward)
    }
}

extern "C" void kernel_launch(void* const* d_in, const int* in_sizes, int n_in,
                              void* d_out, int out_size) {
    const float* in   = (const float*)d_in[0];   // [32, 64, 4096] fp32
    const float* emb  = (const float*)d_in[1];   // [1024, 64] fp32 (pre-normalized)
    const float* embu = (const float*)d_in[2];   // [1024, 64] fp32
    float* out = (float*)d_out;

    vq_argmax_kernel<<<(NB * NT) / (ATPB * 2), ATPB>>>(in, emb, out);
    vq_gather_loss_kernel<<<NPART, TPB>>>(in, emb, embu, out);
    vq_finalize_kernel<<<1, TPB>>>(out);
}

// round 4
// speedup vs baseline: 1.3712x; 1.1580x over previous
#include <cuda_runtime.h>
#include <cuda_bf16.h>
#include <cstdint>

#define NB 32
#define ND 64
#define NT 4096
#define NK 1024
#define NTOK (NB*NT)          // 131072 tokens
#define OUTQ (NB*ND*NT)       // 8388608 quantized elements

#define CBSTRIDE 136          // ushorts per code row: [H(64) | M(64) | pad(8)] = 272B
#define CHUNK_CODES 128
#define NCHUNK (NK/CHUNK_CODES)       // 8
#define CHUNK_BYTES (CHUNK_CODES*CBSTRIDE*2)   // 34816
#define CHUNK_16B (CHUNK_BYTES/16)             // 2176

#define SX_STRIDE 68          // floats per dim row (conflict-free)
#define SMEM_SX_BYTES (64*SX_STRIDE*4)         // 17408
#define SMEM_CB0 SMEM_SX_BYTES
#define SMEM_CB1 (SMEM_CB0 + CHUNK_BYTES)
#define SMEM_TOTAL (SMEM_CB1 + CHUNK_BYTES)    // 87040

#define TAU 1e-3f
#define GT_TPB 256
#define NPART 2048            // gather blocks (64 tokens each)

// Scratch (no allocations allowed)
__device__ int            g_idx[NTOK];
__device__ float          g_part[NPART];
__device__ unsigned short g_cb[NK * CBSTRIDE];   // codebook split [H|M] bf16, padded rows

// ============================ helpers ============================
static __device__ __forceinline__ uint32_t smem_to_u32(const void* p) {
    uint32_t a;
    asm("{ .reg .u64 tmp; cvta.to.shared.u64 tmp, %1; cvt.u32.u64 %0, tmp; }" : "=r"(a) : "l"(p));
    return a;
}
static __device__ __forceinline__ void cp_async16(uint32_t dst, const void* src) {
    asm volatile("cp.async.cg.shared.global [%0], [%1], 16;" :: "r"(dst), "l"(src) : "memory");
}
static __device__ __forceinline__ void cp_commit() {
    asm volatile("cp.async.commit_group;" ::: "memory");
}
static __device__ __forceinline__ void cp_wait1() {
    asm volatile("cp.async.wait_group 1;" ::: "memory");
}
static __device__ __forceinline__ void cp_wait0() {
    asm volatile("cp.async.wait_group 0;" ::: "memory");
}
static __device__ __forceinline__ void ldmatrix_x4(uint32_t& r0, uint32_t& r1,
                                                   uint32_t& r2, uint32_t& r3, uint32_t a) {
    asm volatile("ldmatrix.sync.aligned.m8n8.x4.shared.b16 {%0,%1,%2,%3}, [%4];"
        : "=r"(r0), "=r"(r1), "=r"(r2), "=r"(r3) : "r"(a));
}
static __device__ __forceinline__ void mma_bf16(float& c0, float& c1, float& c2, float& c3,
                                                uint32_t a0, uint32_t a1, uint32_t a2, uint32_t a3,
                                                uint32_t b0, uint32_t b1) {
    asm volatile("mma.sync.aligned.m16n8k16.row.col.f32.bf16.bf16.f32 "
        "{%0,%1,%2,%3}, {%4,%5,%6,%7}, {%8,%9}, {%0,%1,%2,%3};"
        : "+f"(c0), "+f"(c1), "+f"(c2), "+f"(c3)
        : "r"(a0), "r"(a1), "r"(a2), "r"(a3), "r"(b0), "r"(b1));
}
static __device__ __forceinline__ uint32_t packbf(__nv_bfloat16 a, __nv_bfloat16 b) {
    return (uint32_t)__bfloat16_as_ushort(a) | ((uint32_t)__bfloat16_as_ushort(b) << 16);
}
// running top-2 update (ascending idx scan; first-max semantics)
static __device__ __forceinline__ void upd(float v, int idx, float& b, int& bi,
                                           float& s, int& si) {
    if (v > s) {
        if (v > b) { s = b; si = bi; b = v; bi = idx; }
        else       { s = v; si = idx; }
    }
}
// merge another top-2 into mine ((value desc, idx asc) priority)
static __device__ __forceinline__ void mrg(float& b, int& bi, float& s, int& si,
                                           float ob, int obi, float os, int osi) {
    if (ob > b || (ob == b && obi < bi)) {
        if (b > os || (b == os && bi < osi)) { s = b;  si = bi; }
        else                                 { s = os; si = osi; }
        b = ob; bi = obi;
    } else if (ob > s || (ob == s && obi < si)) {
        s = ob; si = obi;
    }
}

// ---------------------------------------------------------------------------
// Kernel 0: split codebook rows into [H | M] bf16, padded stride.
// H = bf16(v); M = bf16(v - H).
// ---------------------------------------------------------------------------
__global__ void vq_prep_kernel(const float* __restrict__ emb)
{
    int i = blockIdx.x * blockDim.x + threadIdx.x;
    if (i >= NK * ND) return;
    int code = i >> 6, d = i & 63;
    float v = emb[i];
    __nv_bfloat16 h = __float2bfloat16_rn(v);
    float r = v - __bfloat162float(h);
    __nv_bfloat16 m = __float2bfloat16_rn(r);
    g_cb[code * CBSTRIDE + d]      = __bfloat16_as_ushort(h);
    g_cb[code * CBSTRIDE + 64 + d] = __bfloat16_as_ushort(m);
}

// ---------------------------------------------------------------------------
// Kernel 1: mma.sync bf16 argmax. CTA = 64 tokens (8 warps x 8 tokens).
// scores = x.e via hH + hM + mH (err <= ~8e-5); top-2 tracked; near-ties
// (margin < TAU) trigger warp-cooperative exact fp32 rescan of all codes.
// ---------------------------------------------------------------------------
__global__ void __launch_bounds__(256, 2) vq_mma_argmax_kernel(
        const float* __restrict__ in, const float* __restrict__ emb,
        float* __restrict__ out)
{
    extern __shared__ float sx[];          // [64 dims][SX_STRIDE] fp32, then code bufs
    const uint32_t sbase = smem_to_u32(sx);
    const int tid  = threadIdx.x;
    const int lane = tid & 31;
    const int w    = tid >> 5;
    const int gid  = lane >> 2;
    const int tig  = lane & 3;

    const int n0 = blockIdx.x * 64;
    const int b  = n0 >> 12;
    const int t0 = n0 & (NT - 1);

    // stage x tile [64 d][64 t] fp32, coalesced
    {
        const float4* src = reinterpret_cast<const float4*>(in + (size_t)b * ND * NT + t0);
#pragma unroll
        for (int k = 0; k < 4; k++) {
            int i = tid + k * 256;
            int d = i >> 4, q = i & 15;
            float4 v = src[(size_t)d * (NT / 4) + q];
            *reinterpret_cast<float4*>(sx + d * SX_STRIDE + q * 4) = v;
        }
    }
    // preload code chunk 0
    for (int i = tid; i < CHUNK_16B; i += 256)
        cp_async16(sbase + SMEM_CB0 + i * 16, (const char*)g_cb + i * 16);
    cp_commit();
    __syncthreads();   // sx visible

    // build token-side fragments (B operand): token = w*8 + gid
    const int tok = w * 8 + gid;
    uint32_t bh[8], bm[8];
#pragma unroll
    for (int j = 0; j < 4; j++) {
        int d0 = j * 16 + 2 * tig;
        float v0 = sx[d0 * SX_STRIDE + tok];
        float v1 = sx[(d0 + 1) * SX_STRIDE + tok];
        float v2 = sx[(d0 + 8) * SX_STRIDE + tok];
        float v3 = sx[(d0 + 9) * SX_STRIDE + tok];
        __nv_bfloat16 h0 = __float2bfloat16_rn(v0), h1 = __float2bfloat16_rn(v1);
        __nv_bfloat16 h2 = __float2bfloat16_rn(v2), h3 = __float2bfloat16_rn(v3);
        bh[2*j]   = packbf(h0, h1);
        bh[2*j+1] = packbf(h2, h3);
        bm[2*j]   = packbf(__float2bfloat16_rn(v0 - __bfloat162float(h0)),
                           __float2bfloat16_rn(v1 - __bfloat162float(h1)));
        bm[2*j+1] = packbf(__float2bfloat16_rn(v2 - __bfloat162float(h2)),
                           __float2bfloat16_rn(v3 - __bfloat162float(h3)));
    }

    float bestv[2] = { -3.0e38f, -3.0e38f }, secv[2] = { -3.0e38f, -3.0e38f };
    int   besti[2] = { 0, 0 },               seci[2] = { 0, 0 };

    const uint32_t lmbase = sbase + (uint32_t)((lane & 15) * (CBSTRIDE * 2) + ((lane >> 4) * 16));

    for (int c = 0; c < NCHUNK; c++) {
        const uint32_t bufo = (c & 1) ? SMEM_CB1 : SMEM_CB0;
        if (c + 1 < NCHUNK) {
            const uint32_t nbufo = (c & 1) ? SMEM_CB0 : SMEM_CB1;
            const char* src = (const char*)g_cb + (size_t)(c + 1) * CHUNK_BYTES;
            for (int i = tid; i < CHUNK_16B; i += 256)
                cp_async16(sbase + nbufo + i * 16, src + i * 16);
            cp_commit();
            cp_wait1();
        } else {
            cp_wait0();
        }
        __syncthreads();

#pragma unroll 2
        for (int mt = 0; mt < 8; mt++) {
            uint32_t sa = lmbase + bufo + (uint32_t)(mt * 16 * CBSTRIDE * 2);
            uint32_t AH[16], AM[16];
#pragma unroll
            for (int jj = 0; jj < 4; jj++) {
                ldmatrix_x4(AH[4*jj], AH[4*jj+1], AH[4*jj+2], AH[4*jj+3], sa + jj * 32);
                ldmatrix_x4(AM[4*jj], AM[4*jj+1], AM[4*jj+2], AM[4*jj+3], sa + 128 + jj * 32);
            }
            float c0 = 0.f, c1 = 0.f, c2 = 0.f, c3 = 0.f;
#pragma unroll
            for (int jj = 0; jj < 4; jj++)   // hH
                mma_bf16(c0, c1, c2, c3, AH[4*jj], AH[4*jj+1], AH[4*jj+2], AH[4*jj+3],
                         bh[2*jj], bh[2*jj+1]);
#pragma unroll
            for (int jj = 0; jj < 4; jj++)   // hM
                mma_bf16(c0, c1, c2, c3, AM[4*jj], AM[4*jj+1], AM[4*jj+2], AM[4*jj+3],
                         bh[2*jj], bh[2*jj+1]);
#pragma unroll
            for (int jj = 0; jj < 4; jj++)   // mH
                mma_bf16(c0, c1, c2, c3, AH[4*jj], AH[4*jj+1], AH[4*jj+2], AH[4*jj+3],
                         bm[2*jj], bm[2*jj+1]);

            const int ib = c * CHUNK_CODES + mt * 16;
            upd(c0, ib + gid,     bestv[0], besti[0], secv[0], seci[0]);
            upd(c1, ib + gid,     bestv[1], besti[1], secv[1], seci[1]);
            upd(c2, ib + gid + 8, bestv[0], besti[0], secv[0], seci[0]);
            upd(c3, ib + gid + 8, bestv[1], besti[1], secv[1], seci[1]);
        }
        __syncthreads();
    }

    // butterfly merge of top-2 across the 8 row-groups (lanes differing in bits 2..4)
#pragma unroll
    for (int off = 4; off <= 16; off <<= 1) {
#pragma unroll
        for (int col = 0; col < 2; col++) {
            float ob  = __shfl_xor_sync(0xffffffffu, bestv[col], off);
            int   obi = __shfl_xor_sync(0xffffffffu, besti[col], off);
            float os  = __shfl_xor_sync(0xffffffffu, secv[col],  off);
            int   osi = __shfl_xor_sync(0xffffffffu, seci[col],  off);
            mrg(bestv[col], besti[col], secv[col], seci[col], ob, obi, os, osi);
        }
    }

    // near-tie rescue: full exact fp32 rescan, warp-cooperative (uniform control)
    unsigned m0 = __ballot_sync(0xffffffffu, (lane < 4) && (bestv[0] - secv[0] < TAU)) & 0xFu;
    unsigned m1 = __ballot_sync(0xffffffffu, (lane < 4) && (bestv[1] - secv[1] < TAU)) & 0xFu;
    if (m0 | m1) {
        for (int l = 0; l < 4; l++) {
#pragma unroll
            for (int col = 0; col < 2; col++) {
                unsigned mm = col ? m1 : m0;
                if ((mm >> l) & 1u) {
                    const int ts = w * 8 + 2 * l + col;   // token slot in block-tile
                    float bb = -3.0e38f; int bi = 0;
                    for (int cc = lane; cc < NK; cc += 32) {
                        const float* e = emb + (size_t)cc * ND;
                        float a0 = 0.f, a1 = 0.f, a2 = 0.f, a3 = 0.f;
#pragma unroll
                        for (int d = 0; d < ND; d += 4) {
                            a0 = fmaf(sx[d * SX_STRIDE + ts],       e[d],     a0);
                            a1 = fmaf(sx[(d + 1) * SX_STRIDE + ts], e[d + 1], a1);
                            a2 = fmaf(sx[(d + 2) * SX_STRIDE + ts], e[d + 2], a2);
                            a3 = fmaf(sx[(d + 3) * SX_STRIDE + ts], e[d + 3], a3);
                        }
                        float v = (a0 + a1) + (a2 + a3);
                        if (v > bb) { bb = v; bi = cc; }
                    }
#pragma unroll
                    for (int off = 16; off; off >>= 1) {
                        float ov = __shfl_xor_sync(0xffffffffu, bb, off);
                        int   oi = __shfl_xor_sync(0xffffffffu, bi, off);
                        if (ov > bb || (ov == bb && oi < bi)) { bb = ov; bi = oi; }
                    }
                    if (lane == l) besti[col] = bi;
                }
            }
        }
    }

    if (lane < 4) {
        const int n = n0 + w * 8 + 2 * lane;
        g_idx[n]     = besti[0];
        g_idx[n + 1] = besti[1];
        out[OUTQ + 2 + n]     = (float)besti[0];
        out[OUTQ + 2 + n + 1] = (float)besti[1];
    }
}

// ---------------------------------------------------------------------------
// Kernel 2: gather quantized output + loss partials, smem-staged so every
// gmem access is coalesced. Block = 64 tokens of one batch.
// commitment_loss == codebook_loss forward == mean((flat - emb_unnorm[idx])^2)
// ---------------------------------------------------------------------------
__global__ void __launch_bounds__(GT_TPB) vq_gather_loss_kernel(
        const float* __restrict__ in, const float* __restrict__ emb,
        const float* __restrict__ embu, float* __restrict__ out)
{
    __shared__ int   sidx[64];
    __shared__ float sq[64 * 65];
    __shared__ float su[64 * 65];

    const int tid = threadIdx.x;
    const int n0  = blockIdx.x * 64;
    const int b   = n0 >> 12;
    const int t0  = n0 & (NT - 1);

    if (tid < 64) sidx[tid] = g_idx[n0 + tid];
    __syncthreads();

    {
        const int tok = tid >> 2;
        const int q   = tid & 3;
        const int code = sidx[tok];
        const float4* e4 = reinterpret_cast<const float4*>(emb  + (size_t)code * ND);
        const float4* u4 = reinterpret_cast<const float4*>(embu + (size_t)code * ND);
#pragma unroll
        for (int j = 0; j < 4; j++) {
            float4 f = e4[q * 4 + j];
            float4 u = u4[q * 4 + j];
            int base = tok * 65 + q * 16 + j * 4;
            sq[base] = f.x; sq[base+1] = f.y; sq[base+2] = f.z; sq[base+3] = f.w;
            su[base] = u.x; su[base+1] = u.y; su[base+2] = u.z; su[base+3] = u.w;
        }
    }
    __syncthreads();

    const int d  = tid >> 2;
    const int j0 = (tid & 3) * 16;
    const size_t gbase = (size_t)b * ND * NT + (size_t)d * NT + t0 + j0;
    float lsum = 0.f;
#pragma unroll
    for (int i = 0; i < 16; i++) {
        float xi = in[gbase + i];
        out[gbase + i] = sq[(j0 + i) * 65 + d];
        float df = xi - su[(j0 + i) * 65 + d];
        lsum += df * df;
    }

#pragma unroll
    for (int o = 16; o; o >>= 1) lsum += __shfl_xor_sync(0xffffffffu, lsum, o);
    __shared__ float ws[GT_TPB / 32];
    if ((tid & 31) == 0) ws[tid >> 5] = lsum;
    __syncthreads();
    if (tid < 32) {
        float v = (tid < GT_TPB / 32) ? ws[tid] : 0.f;
#pragma unroll
        for (int o = 4; o; o >>= 1) v += __shfl_xor_sync(0xffffffffu, v, o);
        if (tid == 0) g_part[blockIdx.x] = v;
    }
}

// ---------------------------------------------------------------------------
// Kernel 3: final loss reduction (double precision), write scalars.
// ---------------------------------------------------------------------------
__global__ void vq_finalize_kernel(float* __restrict__ out)
{
    __shared__ double sd[256];
    double s = 0.0;
    for (int i = threadIdx.x; i < NPART; i += 256) s += (double)g_part[i];
    sd[threadIdx.x] = s;
    __syncthreads();
    for (int o = 128; o; o >>= 1) {
        if (threadIdx.x < o) sd[threadIdx.x] += sd[threadIdx.x + o];
        __syncthreads();
    }
    if (threadIdx.x == 0) {
        float m = (float)(sd[0] / (double)OUTQ);
        out[OUTQ]     = m;   // commitment_loss
        out[OUTQ + 1] = m;   // codebook_loss (numerically identical forward)
    }
}

extern "C" void kernel_launch(void* const* d_in, const int* in_sizes, int n_in,
                              void* d_out, int out_size) {
    const float* in   = (const float*)d_in[0];   // [32, 64, 4096] fp32
    const float* emb  = (const float*)d_in[1];   // [1024, 64] fp32 (pre-normalized)
    const float* embu = (const float*)d_in[2];   // [1024, 64] fp32
    float* out = (float*)d_out;

    static int configured = 0;
    if (!configured) {
        cudaFuncSetAttribute(vq_mma_argmax_kernel,
                             cudaFuncAttributeMaxDynamicSharedMemorySize, SMEM_TOTAL);
        configured = 1;
    }

    vq_prep_kernel<<<(NK * ND) / 256, 256>>>(emb);
    vq_mma_argmax_kernel<<<NTOK / 64, 256, SMEM_TOTAL>>>(in, emb, out);
    vq_gather_loss_kernel<<<NPART, GT_TPB>>>(in, emb, embu, out);
    vq_finalize_kernel<<<1, 256>>>(out);
}